// round 1
// baseline (speedup 1.0000x reference)
#include <cuda_runtime.h>
#include <cuda_bf16.h>
#include <math.h>

// ---------------------------------------------------------------------------
// Problem constants
// ---------------------------------------------------------------------------
#define Bv    32
#define NCLS  20
#define Tt    2048
#define Dd    2048
#define Ll    128
#define NPAIR 16
#define GAMMA_F 0.1f
#define INV_GAMMA_F 10.0f
#define THRES_F 0.5f

// ---------------------------------------------------------------------------
// Device scratch (no allocations allowed)
// ---------------------------------------------------------------------------
// rnorm tensors: 0=lcs full, 1=act first half, 2=act second half,
//                3=bak first half, 4=bak second half   (each [32*128])
__device__ float g_rnorm[5 * Bv * Ll];
__device__ float g_sim_lcs[32 * Ll * Ll];   // transformed s for LCS DP
__device__ float g_sim_m[32 * Ll * Ll];     // FSD m
__device__ float g_sim_g[32 * Ll * Ll];     // FSD g
// partial sums: 0 cls, 1 guide, 2 feat, 3 sparse, 4 posLCS, 5 negLCS,
//               6 act_act, 7 act_bak
__device__ float g_partial[8];

// ---------------------------------------------------------------------------
// init: zero the partial accumulators
// ---------------------------------------------------------------------------
__global__ void k_init() {
    if (threadIdx.x < 8) g_partial[threadIdx.x] = 0.0f;
}

// ---------------------------------------------------------------------------
// row reciprocal norms: warp per row
// ---------------------------------------------------------------------------
__global__ void k_norms(const float* __restrict__ lcs,
                        const float* __restrict__ act,
                        const float* __restrict__ bak) {
    int warp = (blockIdx.x * blockDim.x + threadIdx.x) >> 5;
    int lane = threadIdx.x & 31;
    const int ROWS = Bv * Ll;                 // 4096
    if (warp >= 5 * ROWS) return;
    int tensor = warp / ROWS;
    int r      = warp % ROWS;

    const float* base; int off, len;
    switch (tensor) {
        case 0: base = lcs; off = 0;    len = 2048; break;
        case 1: base = act; off = 0;    len = 1024; break;
        case 2: base = act; off = 1024; len = 1024; break;
        case 3: base = bak; off = 0;    len = 1024; break;
        default: base = bak; off = 1024; len = 1024; break;
    }
    const float* p = base + (size_t)r * Dd + off;
    float s = 0.0f;
    for (int k = lane * 4; k < len; k += 128) {
        float4 v = *(const float4*)(p + k);
        s += v.x * v.x + v.y * v.y + v.z * v.z + v.w * v.w;
    }
#pragma unroll
    for (int o = 16; o > 0; o >>= 1)
        s += __shfl_xor_sync(0xffffffffu, s, o);
    if (lane == 0) g_rnorm[tensor * ROWS + r] = rsqrtf(s);
}

// ---------------------------------------------------------------------------
// Similarity GEMMs.  96 sims: [0,32) LCS (K=2048), [32,96) FSD m/g (K=1024).
// Block = one 128x64 output tile (2 blocks per sim). 256 threads.
// BM=128, BN=64, BK=16, TM=8, TN=4.
// ---------------------------------------------------------------------------
#define BM 128
#define BN 64
#define BK 16

__global__ __launch_bounds__(256, 2)
void k_gemm(const float* __restrict__ lcs,
            const float* __restrict__ act,
            const float* __restrict__ bak,
            const int* __restrict__ pos,
            const int* __restrict__ neg) {
    int blk = blockIdx.x;           // 0..191
    int sim = blk >> 1;
    int colTile = (blk & 1) * BN;

    const float *Abase, *Bbase, *rnA, *rnB;
    float* out;
    int Ksteps;
    int do_transform;

    if (sim < 32) {
        int p  = sim;
        int i0 = (p < 16) ? pos[2 * p]     : neg[2 * (p - 16)];
        int i1 = (p < 16) ? pos[2 * p + 1] : neg[2 * (p - 16) + 1];
        Abase = lcs + (size_t)i0 * Ll * Dd;
        Bbase = lcs + (size_t)i1 * Ll * Dd;
        rnA = g_rnorm + 0 * (Bv * Ll) + i0 * Ll;
        rnB = g_rnorm + 0 * (Bv * Ll) + i1 * Ll;
        out = g_sim_lcs + (size_t)p * Ll * Ll;
        Ksteps = 2048 / BK;
        do_transform = 1;
    } else {
        int f = sim - 32;
        int p = f >> 1;
        int half = f & 1;
        int i0 = (p < 16) ? pos[2 * p]     : neg[2 * (p - 16)];
        int i1 = (p < 16) ? pos[2 * p + 1] : neg[2 * (p - 16) + 1];
        Abase = act + (size_t)i0 * Ll * Dd + half * 1024;
        rnA = g_rnorm + (1 + half) * (Bv * Ll) + i0 * Ll;
        if (p < 16) {
            Bbase = act + (size_t)i1 * Ll * Dd + half * 1024;
            rnB = g_rnorm + (1 + half) * (Bv * Ll) + i1 * Ll;
        } else {
            Bbase = bak + (size_t)i1 * Ll * Dd + half * 1024;
            rnB = g_rnorm + (3 + half) * (Bv * Ll) + i1 * Ll;
        }
        out = (half ? g_sim_g : g_sim_m) + (size_t)p * Ll * Ll;
        Ksteps = 1024 / BK;
        do_transform = 0;
    }
    Bbase += (size_t)colTile * Dd;

    __shared__ float As[BK][BM];   // [k][m]
    __shared__ float Bs[BK][BN];   // [k][n]

    int t  = threadIdx.x;
    int tx = t & 15;               // 0..15 -> cols tx*4
    int ty = t >> 4;               // 0..15 -> rows ty*8

    float acc[8][4];
#pragma unroll
    for (int i = 0; i < 8; ++i)
#pragma unroll
        for (int j = 0; j < 4; ++j) acc[i][j] = 0.0f;

    for (int kt = 0; kt < Ksteps; ++kt) {
        int k0 = kt * BK;
        // load A: 128 rows x 16 k = 512 float4, 2 per thread
#pragma unroll
        for (int it = 0; it < 2; ++it) {
            int s   = t + it * 256;
            int row = s >> 2;
            int kc  = (s & 3) * 4;
            float4 v = *(const float4*)(Abase + (size_t)row * Dd + k0 + kc);
            As[kc + 0][row] = v.x;
            As[kc + 1][row] = v.y;
            As[kc + 2][row] = v.z;
            As[kc + 3][row] = v.w;
        }
        // load B: 64 rows x 16 k = 256 float4, 1 per thread
        {
            int row = t >> 2;
            int kc  = (t & 3) * 4;
            float4 v = *(const float4*)(Bbase + (size_t)row * Dd + k0 + kc);
            Bs[kc + 0][row] = v.x;
            Bs[kc + 1][row] = v.y;
            Bs[kc + 2][row] = v.z;
            Bs[kc + 3][row] = v.w;
        }
        __syncthreads();

#pragma unroll
        for (int k = 0; k < BK; ++k) {
            float4 a0 = *(const float4*)&As[k][ty * 8];
            float4 a1 = *(const float4*)&As[k][ty * 8 + 4];
            float4 b0 = *(const float4*)&Bs[k][tx * 4];
            float av[8] = {a0.x, a0.y, a0.z, a0.w, a1.x, a1.y, a1.z, a1.w};
            float bv[4] = {b0.x, b0.y, b0.z, b0.w};
#pragma unroll
            for (int i = 0; i < 8; ++i)
#pragma unroll
                for (int j = 0; j < 4; ++j)
                    acc[i][j] = fmaf(av[i], bv[j], acc[i][j]);
        }
        __syncthreads();
    }

    float ra[8], rb[4];
#pragma unroll
    for (int i = 0; i < 8; ++i) ra[i] = rnA[ty * 8 + i];
#pragma unroll
    for (int j = 0; j < 4; ++j) rb[j] = rnB[colTile + tx * 4 + j];

#pragma unroll
    for (int i = 0; i < 8; ++i) {
        int row = ty * 8 + i;
#pragma unroll
        for (int j = 0; j < 4; ++j) {
            int col = colTile + tx * 4 + j;
            float v = acc[i][j] * ra[i] * rb[j];
            if (do_transform) v = fmaxf(0.0f, v - 0.8f) * 5.0f;
            out[row * Ll + col] = v;
        }
    }
}

// ---------------------------------------------------------------------------
// LCS wavefront DP. One block (128 threads) per pair. smem: S[128*128] + C[129*130]
// ---------------------------------------------------------------------------
__global__ void k_lcs_dp() {
    extern __shared__ float sm[];
    float* S = sm;                  // 16384
    float* C = sm + Ll * Ll;        // 129*130

    int p = blockIdx.x;
    int t = threadIdx.x;            // 0..127
    const float* src = g_sim_lcs + (size_t)p * Ll * Ll;
    for (int idx = t * 4; idx < Ll * Ll; idx += 512)
        *(float4*)(S + idx) = *(const float4*)(src + idx);

    // boundaries
    C[t] = 0.0f;
    if (t == 0) C[128] = 0.0f;
    C[(t + 1) * 130] = 0.0f;
    __syncthreads();

    int i = t + 1;
    for (int d = 2; d <= 2 * Ll; ++d) {
        if (i >= d - Ll && i <= d - 1) {
            int j = d - i;
            float s  = S[(i - 1) * Ll + (j - 1)];
            float cd = C[(i - 1) * 130 + (j - 1)];
            float cu = C[(i - 1) * 130 + j];
            float cl = C[i * 130 + (j - 1)];
            float nv = (s > THRES_F) ? (cd + s) : fmaxf(cu, cl);
            C[i * 130 + j] = nv;
        }
        __syncthreads();
    }
    if (t == 127)
        atomicAdd(&g_partial[p < 16 ? 4 : 5], C[128 * 130 + 128]);
}

// ---------------------------------------------------------------------------
// FSD soft-DP. One block per pair. smem: M + G + C
// ---------------------------------------------------------------------------
__global__ void k_fsd_dp() {
    extern __shared__ float sm[];
    float* M = sm;                         // 16384
    float* G = sm + Ll * Ll;               // 16384
    float* C = sm + 2 * Ll * Ll;           // 129*130

    int p = blockIdx.x;
    int t = threadIdx.x;
    const float* msrc = g_sim_m + (size_t)p * Ll * Ll;
    const float* gsrc = g_sim_g + (size_t)p * Ll * Ll;
    for (int idx = t * 4; idx < Ll * Ll; idx += 512) {
        *(float4*)(M + idx) = *(const float4*)(msrc + idx);
        *(float4*)(G + idx) = *(const float4*)(gsrc + idx);
    }
    C[t] = 0.0f;
    if (t == 0) C[128] = 0.0f;
    C[(t + 1) * 130] = 0.0f;
    __syncthreads();

    int i = t + 1;
    for (int d = 2; d <= 2 * Ll; ++d) {
        if (i >= d - Ll && i <= d - 1) {
            int j = d - i;
            float mv = M[(i - 1) * Ll + (j - 1)];
            float gv = G[(i - 1) * Ll + (j - 1)];
            float cd = C[(i - 1) * 130 + (j - 1)];
            float cu = C[(i - 1) * 130 + j];
            float cl = C[i * 130 + (j - 1)];
            float x1 = gv + cu;
            float x2 = gv + cl;
            float mx = fmaxf(cd, fmaxf(x1, x2));
            float ss = __expf((cd - mx) * INV_GAMMA_F)
                     + __expf((x1 - mx) * INV_GAMMA_F)
                     + __expf((x2 - mx) * INV_GAMMA_F);
            C[i * 130 + j] = mv + mx + GAMMA_F * __logf(ss);
        }
        __syncthreads();
    }
    if (t == 127)
        atomicAdd(&g_partial[p < 16 ? 6 : 7], C[128 * 130 + 128]);
}

// ---------------------------------------------------------------------------
// Small ACM losses. One block per batch element.
// ---------------------------------------------------------------------------
__global__ void k_small(const float* __restrict__ xi,   // act_inst_cls [32,21]
                        const float* __restrict__ xc,   // act_cont_cls
                        const float* __restrict__ xb,   // act_back_cls
                        const float* __restrict__ vid,  // [32,20]
                        const float* __restrict__ att,  // [32,2048,3]
                        const float* __restrict__ fi,   // act_inst_feat [32,2048]
                        const float* __restrict__ fc,
                        const float* __restrict__ fb,
                        const float* __restrict__ cas)  // [32,2048,21]
{
    __shared__ float red[256];
    int b = blockIdx.x;
    int tid = threadIdx.x;

    float guide = 0.0f, sparse = 0.0f, si2 = 0.0f, sc2 = 0.0f, sb2 = 0.0f;
    for (int tt = tid; tt < Tt; tt += 256) {
        float cas20 = cas[((size_t)b * Tt + tt) * (NCLS + 1) + NCLS];
        float a0 = att[((size_t)b * Tt + tt) * 3 + 0];
        float a1 = att[((size_t)b * Tt + tt) * 3 + 1];
        guide  += fabsf(1.0f - cas20 - a0);
        sparse += a0 + a1;
    }
    for (int k = tid; k < Dd; k += 256) {
        float vi = fi[(size_t)b * Dd + k];
        float vc = fc[(size_t)b * Dd + k];
        float vb = fb[(size_t)b * Dd + k];
        si2 += vi * vi; sc2 += vc * vc; sb2 += vb * vb;
    }

    float vals[5] = {guide, sparse, si2, sc2, sb2};
#pragma unroll
    for (int v = 0; v < 5; ++v) {
        red[tid] = vals[v];
        __syncthreads();
        for (int s = 128; s > 0; s >>= 1) {
            if (tid < s) red[tid] += red[tid + s];
            __syncthreads();
        }
        vals[v] = red[0];
        __syncthreads();
    }

    if (tid == 0) {
        float ni = sqrtf(vals[2]);
        float nc = sqrtf(vals[3]);
        float nb = sqrtf(vals[4]);
        float f1 = fmaxf(50.0f - ni + nc, 0.0f);
        float f2 = fmaxf(50.0f - nc + nb, 0.0f);
        float feat = (f1 + f2 + nb) * (f1 + f2 + nb);

        // cls
        float sv = 0.0f, s_i = 0.0f, s_c = 0.0f;
        for (int c = 0; c < NCLS; ++c) {
            float l = vid[b * NCLS + c];
            sv  += l;
            s_i += l * logf(xi[b * (NCLS + 1) + c] + 1e-45f);
            s_c += l * logf(xc[b * (NCLS + 1) + c] + 1e-45f);
        }
        float inst_b = -s_i / sv;
        float cont_b = -(s_c + logf(xc[b * (NCLS + 1) + NCLS] + 1e-45f)) / (sv + 1.0f);
        float back_b = -logf(xb[b * (NCLS + 1) + NCLS] + 1e-45f);
        float cls_b = inst_b + cont_b + back_b;

        atomicAdd(&g_partial[0], cls_b);
        atomicAdd(&g_partial[1], vals[0]);
        atomicAdd(&g_partial[2], feat);
        atomicAdd(&g_partial[3], vals[1]);
    }
}

// ---------------------------------------------------------------------------
// Combine
// ---------------------------------------------------------------------------
__global__ void k_combine(float* out) {
    float cls    = g_partial[0] / 32.0f;
    float guide  = g_partial[1] / 32.0f;
    float feat   = g_partial[2] / 32.0f;
    float sparse = g_partial[3] / 64.0f;
    float acm = cls + 1.0f * guide + 5e-5f * feat + 2e-4f * sparse;
    float lcs_loss = (g_partial[5] - g_partial[4]) / 16.0f;
    float fsd_loss = (g_partial[7] - g_partial[6]) / 16.0f;
    out[0] = acm + 0.1f * lcs_loss + 0.1f * fsd_loss;
}

// ---------------------------------------------------------------------------
// Launch
// ---------------------------------------------------------------------------
extern "C" void kernel_launch(void* const* d_in, const int* in_sizes, int n_in,
                              void* d_out, int out_size) {
    const float* xi  = (const float*)d_in[0];
    const float* xc  = (const float*)d_in[1];
    const float* xb  = (const float*)d_in[2];
    const float* vid = (const float*)d_in[3];
    const float* att = (const float*)d_in[4];
    const float* fi  = (const float*)d_in[5];
    const float* fc  = (const float*)d_in[6];
    const float* fb  = (const float*)d_in[7];
    const float* cas = (const float*)d_in[8];
    const float* lcs = (const float*)d_in[9];
    const float* act = (const float*)d_in[10];
    const float* bak = (const float*)d_in[11];
    const int*   pos = (const int*)d_in[12];
    const int*   neg = (const int*)d_in[13];
    float* out = (float*)d_out;

    const int lcs_smem = (Ll * Ll + 129 * 130) * (int)sizeof(float);       // ~132.6 KB
    const int fsd_smem = (2 * Ll * Ll + 129 * 130) * (int)sizeof(float);   // ~198.2 KB
    cudaFuncSetAttribute(k_lcs_dp, cudaFuncAttributeMaxDynamicSharedMemorySize, lcs_smem);
    cudaFuncSetAttribute(k_fsd_dp, cudaFuncAttributeMaxDynamicSharedMemorySize, fsd_smem);

    k_init<<<1, 32>>>();
    // 5 tensors x 4096 rows = 20480 warps; 8 warps/block
    k_norms<<<2560, 256>>>(lcs, act, bak);
    k_gemm<<<192, 256>>>(lcs, act, bak, pos, neg);
    k_fsd_dp<<<32, 128, fsd_smem>>>();
    k_lcs_dp<<<32, 128, lcs_smem>>>();
    k_small<<<32, 256>>>(xi, xc, xb, vid, att, fi, fc, fb, cas);
    k_combine<<<1, 1>>>(out);
}